// round 11
// baseline (speedup 1.0000x reference)
#include <cuda_runtime.h>
#include <cstdint>

// out[r,c] = sign(r) * x_real[r,c]   (real-part coercion; rel_err=0.0 confirmed)
// sign(r) = -1 iff ( popc(r & (r>>1)) + ((r & 1) & (r >> 12)) ) is odd.
//
// R11: persistent single-wave kernel. MLP ladder settled at 2 (R9: 35.6us,
// 75.5% DRAM). Now remove the ~14 wave transitions of the 16384-CTA launch:
// 1024 resident CTAs (<= 1184 = 148 SMs x 8 CTA occupancy), each owning
// 8192 consecutive float4s, 16 iterations of the MLP=2 body. Plain LDG/STG
// (.cs hints proven harmful in R7/R8).

static constexpr unsigned N_WIRES = 13;

__device__ __forceinline__ float row_sign(unsigned row) {
    unsigned parity = __popc(row & (row >> 1)) + ((row & 1u) & (row >> (N_WIRES - 1)));
    return (parity & 1u) ? -1.0f : 1.0f;
}

// Each block owns chunk_v4 consecutive float4s starting at blockIdx*chunk_v4.
// Inner loop: 2 independent float4 loads per iteration (MLP=2), no predicates
// (host guarantees chunk_v4 % 512 == 0).
__global__ __launch_bounds__(256) void cz_real_persist(
    const float4* __restrict__ xr,
    float4* __restrict__ out,
    unsigned row_shift,        // log2(batch/4)
    unsigned chunk_v4)         // float4s per block, multiple of 512
{
    unsigned base = blockIdx.x * chunk_v4 + threadIdx.x;
    unsigned end  = blockIdx.x * chunk_v4 + chunk_v4;

    #pragma unroll 1
    for (unsigned i0 = base; i0 < end; i0 += 512u) {
        unsigned i1 = i0 + 256u;

        float4 v0 = xr[i0];
        float4 v1 = xr[i1];

        float s0 = row_sign(i0 >> row_shift);
        float s1 = row_sign(i1 >> row_shift);

        v0.x *= s0; v0.y *= s0; v0.z *= s0; v0.w *= s0;
        v1.x *= s1; v1.y *= s1; v1.z *= s1; v1.w *= s1;

        out[i0] = v0;
        out[i1] = v1;
    }
}

// Scalar path: tail [start, n) or full problem for odd shapes/alignment.
__global__ __launch_bounds__(256) void cz_real_scalar(
    const float* __restrict__ xr,
    float* __restrict__ out,
    unsigned start, unsigned n_elems, unsigned batch)
{
    unsigned i = start + blockIdx.x * 256u + threadIdx.x;
    if (i >= n_elems) return;
    float s = row_sign(i / batch);
    out[i] = s * xr[i];
}

extern "C" void kernel_launch(void* const* d_in, const int* in_sizes, int n_in,
                              void* d_out, int out_size)
{
    if (n_in < 1) return;
    const void* xr = d_in[0];

    unsigned E = (unsigned)out_size;
    if ((unsigned)in_sizes[0] < E) E = (unsigned)in_sizes[0];
    if (E == 0) return;

    unsigned batch = E >> N_WIRES;          // columns (4096 nominally)
    if (batch == 0) batch = 1;

    bool pow2_batch4 = (batch % 4u == 0) &&
                       (((batch / 4u) & (batch / 4u - 1u)) == 0);
    bool vec_ok =
        (((uintptr_t)xr) % 16u == 0) &&
        (((uintptr_t)d_out) % 16u == 0) &&
        pow2_batch4 && (E % 4u == 0);

    if (vec_ok) {
        unsigned vpr = batch / 4u;                    // 1024 nominally
        unsigned row_shift = 0;
        while ((1u << row_shift) < vpr) row_shift++;  // log2 (vpr is pow2)

        unsigned n_vec = E / 4u;                      // 2^23 nominally

        // Single resident wave: 1024 CTAs if work divides evenly into
        // 512-float4 iterations; otherwise fall back to the R9 grid shape.
        unsigned grid, chunk;
        if (n_vec % (1024u * 512u) == 0) {
            grid  = 1024u;
            chunk = n_vec / 1024u;                    // 8192 nominally
        } else if (n_vec % 512u == 0) {
            grid  = n_vec / 512u;
            chunk = 512u;
        } else {
            grid = 0; chunk = 0;
        }

        if (grid) {
            cz_real_persist<<<grid, 256>>>(
                (const float4*)xr, (float4*)d_out, row_shift, chunk);
            unsigned done = grid * chunk * 4u;        // floats covered (=E here)
            if (done < E)
                cz_real_scalar<<<((E - done) + 255u) / 256u, 256>>>(
                    (const float*)xr, (float*)d_out, done, E, batch);
        } else {
            cz_real_scalar<<<(E + 255u) / 256u, 256>>>(
                (const float*)xr, (float*)d_out, 0, E, batch);
        }
    } else {
        cz_real_scalar<<<(E + 255u) / 256u, 256>>>(
            (const float*)xr, (float*)d_out, 0, E, batch);
    }
}

// round 12
// speedup vs baseline: 1.1243x; 1.1243x over previous
#include <cuda_runtime.h>
#include <cstdint>

// out[r,c] = sign(r) * x_real[r,c]   (real-part coercion; rel_err=0.0 confirmed)
// sign(r) = -1 iff ( popc(r & (r>>1)) + ((r & 1) & (r >> 12)) ) is odd.
//
// R12: revert to R9's measured optimum (MLP=2, plain LDG/STG, 16384x256
// exact cover — 35.6us / 75.5% DRAM; persistent R11 regressed to 39.4us via
// 1024/148 CTA imbalance). One refinement: apply the sign as an integer XOR
// of the fp32 sign bit (LOP3) instead of FMULs — exact same bits, shorter
// dependent chain, fma pipe ~0.

static constexpr unsigned N_WIRES = 13;

// 0x80000000 if parity odd (flip sign), else 0.
__device__ __forceinline__ unsigned row_sign_mask(unsigned row) {
    unsigned parity = __popc(row & (row >> 1)) + ((row & 1u) & (row >> (N_WIRES - 1)));
    return (parity & 1u) << 31;
}

__device__ __forceinline__ uint4 xor_sign(uint4 v, unsigned m) {
    v.x ^= m; v.y ^= m; v.z ^= m; v.w ^= m;
    return v;
}

// Exact cover: each block owns 512 consecutive float4s; thread t handles
// base+t and base+256+t (MLP=2). No bounds checks (host guarantees cover).
__global__ __launch_bounds__(256) void cz_real_v2x(
    const uint4* __restrict__ xr,
    uint4* __restrict__ out,
    unsigned row_shift)        // log2(batch/4)
{
    unsigned i0 = blockIdx.x * 512u + threadIdx.x;
    unsigned i1 = i0 + 256u;

    uint4 v0 = xr[i0];
    uint4 v1 = xr[i1];

    unsigned m0 = row_sign_mask(i0 >> row_shift);
    unsigned m1 = row_sign_mask(i1 >> row_shift);

    out[i0] = xor_sign(v0, m0);
    out[i1] = xor_sign(v1, m1);
}

// Scalar path: tail [start, n) or full problem for odd shapes/alignment.
__global__ __launch_bounds__(256) void cz_real_scalar(
    const float* __restrict__ xr,
    float* __restrict__ out,
    unsigned start, unsigned n_elems, unsigned batch)
{
    unsigned i = start + blockIdx.x * 256u + threadIdx.x;
    if (i >= n_elems) return;
    unsigned row = i / batch;
    unsigned parity = __popc(row & (row >> 1)) + ((row & 1u) & (row >> (N_WIRES - 1)));
    float s = (parity & 1u) ? -1.0f : 1.0f;
    out[i] = s * xr[i];
}

extern "C" void kernel_launch(void* const* d_in, const int* in_sizes, int n_in,
                              void* d_out, int out_size)
{
    if (n_in < 1) return;
    const void* xr = d_in[0];

    unsigned E = (unsigned)out_size;
    if ((unsigned)in_sizes[0] < E) E = (unsigned)in_sizes[0];
    if (E == 0) return;

    unsigned batch = E >> N_WIRES;          // columns (4096 nominally)
    if (batch == 0) batch = 1;

    bool pow2_batch4 = (batch % 4u == 0) &&
                       (((batch / 4u) & (batch / 4u - 1u)) == 0);
    bool vec_ok =
        (((uintptr_t)xr) % 16u == 0) &&
        (((uintptr_t)d_out) % 16u == 0) &&
        pow2_batch4 && (E % 4u == 0);

    if (vec_ok) {
        unsigned vpr = batch / 4u;                    // 1024 nominally
        unsigned row_shift = 0;
        while ((1u << row_shift) < vpr) row_shift++;  // log2 (vpr is pow2)

        unsigned n_vec = E / 4u;                      // 2^23 nominally
        unsigned full_blocks = n_vec / 512u;          // 16384 nominally
        if (full_blocks)
            cz_real_v2x<<<full_blocks, 256>>>(
                (const uint4*)xr, (uint4*)d_out, row_shift);

        unsigned done = full_blocks * 512u * 4u;      // floats covered
        if (done < E)                                  // tail (none nominally)
            cz_real_scalar<<<((E - done) + 255u) / 256u, 256>>>(
                (const float*)xr, (float*)d_out, done, E, batch);
    } else {
        cz_real_scalar<<<(E + 255u) / 256u, 256>>>(
            (const float*)xr, (float*)d_out, 0, E, batch);
    }
}